// round 8
// baseline (speedup 1.0000x reference)
#include <cuda_runtime.h>
#include <cuda_bf16.h>
#include <stdint.h>

#define NH   12
#define SQ   1024
#define NB   8
#define HID  768
#define MROWS (NB*SQ)   // 8192
#define LDT  40         // GEMM: padded bf16 row stride (32 k-cols + 8)
#define ALD  72         // attention K/V tiles: 64 d-cols + 8 pad

#define GSTG_ELEMS (4*128*LDT)          // one GEMM stage: Ahi,Alo,Bhi,Blo
#define GSTG_BYTES (GSTG_ELEMS*2)       // 40960
#define GSMEM_BYTES (2*GSTG_BYTES)      // 81920 dynamic

// Scratch (allocation-free rule: device globals)
__device__ float g_q[MROWS*HID];
__device__ float g_k[MROWS*HID];
__device__ float g_v[MROWS*HID];
__device__ float g_attn[MROWS*HID];
__device__ float g_bias[(size_t)NB*SQ*SQ];   // sp+ed fused, mask applied

// ---------------------------------------------------------------------------
// Tensor-core primitives
// ---------------------------------------------------------------------------
__device__ __forceinline__ void mma_bf16(float* d, const uint32_t* a, const uint32_t* b)
{
    asm volatile(
        "mma.sync.aligned.m16n8k16.row.col.f32.bf16.bf16.f32 "
        "{%0,%1,%2,%3},{%4,%5,%6,%7},{%8,%9},{%0,%1,%2,%3};"
        : "+f"(d[0]), "+f"(d[1]), "+f"(d[2]), "+f"(d[3])
        : "r"(a[0]), "r"(a[1]), "r"(a[2]), "r"(a[3]), "r"(b[0]), "r"(b[1]));
}
__device__ __forceinline__ void ldsm4(uint32_t* r, uint32_t addr)
{
    asm volatile("ldmatrix.sync.aligned.m8n8.x4.shared.b16 {%0,%1,%2,%3},[%4];"
                 : "=r"(r[0]), "=r"(r[1]), "=r"(r[2]), "=r"(r[3]) : "r"(addr));
}
__device__ __forceinline__ void ldsm2(uint32_t* r, uint32_t addr)
{
    asm volatile("ldmatrix.sync.aligned.m8n8.x2.shared.b16 {%0,%1},[%2];"
                 : "=r"(r[0]), "=r"(r[1]) : "r"(addr));
}
__device__ __forceinline__ void ldsm2t(uint32_t* r, uint32_t addr)
{
    asm volatile("ldmatrix.sync.aligned.m8n8.x2.trans.shared.b16 {%0,%1},[%2];"
                 : "=r"(r[0]), "=r"(r[1]) : "r"(addr));
}
__device__ __forceinline__ float fexp2(float x)
{
    float y;
    asm("ex2.approx.ftz.f32 %0, %1;" : "=f"(y) : "f"(x));
    return y;
}
#define LOG2E 1.4426950408889634f

// split x into hi (bf16) + lo (bf16 of residual)
__device__ __forceinline__ void split4(float4 v, __nv_bfloat162& h0, __nv_bfloat162& h1,
                                       __nv_bfloat162& l0, __nv_bfloat162& l1)
{
    __nv_bfloat16 hx = __float2bfloat16_rn(v.x);
    __nv_bfloat16 hy = __float2bfloat16_rn(v.y);
    __nv_bfloat16 hz = __float2bfloat16_rn(v.z);
    __nv_bfloat16 hw = __float2bfloat16_rn(v.w);
    h0 = __nv_bfloat162(hx, hy);
    h1 = __nv_bfloat162(hz, hw);
    l0 = __nv_bfloat162(__float2bfloat16_rn(v.x - __bfloat162float(hx)),
                        __float2bfloat16_rn(v.y - __bfloat162float(hy)));
    l1 = __nv_bfloat162(__float2bfloat16_rn(v.z - __bfloat162float(hz)),
                        __float2bfloat16_rn(v.w - __bfloat162float(hw)));
}
__device__ __forceinline__ void split2(float x, float y, uint32_t& hi, uint32_t& lo)
{
    __nv_bfloat16 hx = __float2bfloat16_rn(x);
    __nv_bfloat16 hy = __float2bfloat16_rn(y);
    __nv_bfloat162 h(hx, hy);
    __nv_bfloat162 l(__float2bfloat16_rn(x - __bfloat162float(hx)),
                     __float2bfloat16_rn(y - __bfloat162float(hy)));
    hi = *(uint32_t*)&h;
    lo = *(uint32_t*)&l;
}

// ---------------------------------------------------------------------------
// Fused bias precompute: g_bias = sp + ed, mask -> -1e30
// ---------------------------------------------------------------------------
__global__ void __launch_bounds__(256) bias_kernel(const float* __restrict__ sp,
                                                   const float* __restrict__ ed,
                                                   const unsigned char* __restrict__ mk)
{
    const size_t i = (size_t)blockIdx.x * 256 + threadIdx.x;   // float4 index
    float4 s = ((const float4*)sp)[i];
    float4 e = ((const float4*)ed)[i];
    uint32_t m = ((const uint32_t*)mk)[i];
    float4 o;
    o.x = (m & 0x000000ffu) ? -1e30f : s.x + e.x;
    o.y = (m & 0x0000ff00u) ? -1e30f : s.y + e.y;
    o.z = (m & 0x00ff0000u) ? -1e30f : s.z + e.z;
    o.w = (m & 0xff000000u) ? -1e30f : s.w + e.w;
    ((float4*)g_bias)[i] = o;
}

// ---------------------------------------------------------------------------
// bf16-split tensor-core GEMM with 2-stage smem pipeline.
// out[m][n] = sum_k X[m][k]*W[n][k] + bias[n]. CTA tile 128x128, BK=32.
// ---------------------------------------------------------------------------
__device__ __forceinline__ void store_stage(__nv_bfloat16* st, const float4* pa,
                                            const float4* pb, int lrow, int lch)
{
    __nv_bfloat16* sAhi = st;
    __nv_bfloat16* sAlo = st + 128*LDT;
    __nv_bfloat16* sBhi = st + 2*128*LDT;
    __nv_bfloat16* sBlo = st + 3*128*LDT;
#pragma unroll
    for (int i = 0; i < 4; i++) {
        int e = (lrow + 32 * i) * LDT + lch;
        __nv_bfloat162 h0, h1, l0, l1;
        split4(pa[i], h0, h1, l0, l1);
        *(__nv_bfloat162*)(sAhi + e)     = h0;
        *(__nv_bfloat162*)(sAhi + e + 2) = h1;
        *(__nv_bfloat162*)(sAlo + e)     = l0;
        *(__nv_bfloat162*)(sAlo + e + 2) = l1;
        split4(pb[i], h0, h1, l0, l1);
        *(__nv_bfloat162*)(sBhi + e)     = h0;
        *(__nv_bfloat162*)(sBhi + e + 2) = h1;
        *(__nv_bfloat162*)(sBlo + e)     = l0;
        *(__nv_bfloat162*)(sBlo + e + 2) = l1;
    }
}

__device__ void gemm_mma(const float* __restrict__ X, const float* __restrict__ W,
                         const float* __restrict__ bias, float* __restrict__ out)
{
    extern __shared__ __align__(16) __nv_bfloat16 dsm[];

    const int tid  = threadIdx.x;
    const int lane = tid & 31;
    const int wid  = tid >> 5;
    const int wm   = (wid >> 2) * 64;
    const int wn   = (wid & 3) * 32;
    const int m0   = blockIdx.x * 128;
    const int n0   = blockIdx.y * 128;

    const int lrow = tid >> 3;
    const int lch  = (tid & 7) * 4;

    float acc[4][4][4];
#pragma unroll
    for (int mt = 0; mt < 4; mt++)
#pragma unroll
        for (int nt = 0; nt < 4; nt++)
#pragma unroll
            for (int r = 0; r < 4; r++) acc[mt][nt][r] = 0.f;

    const uint32_t base = (uint32_t)__cvta_generic_to_shared(dsm);
    const uint32_t aOff = ((wm + (lane & 15)) * LDT + (lane >> 4) * 8) * 2;
    const uint32_t bOff = ((wn + (lane & 7)) * LDT + ((lane >> 3) & 1) * 8) * 2;
    const uint32_t ALO_B = 128*LDT*2;
    const uint32_t BHI_B = 2*128*LDT*2;
    const uint32_t BLO_B = 3*128*LDT*2;

    const float* Xp = X + (size_t)(m0 + lrow) * HID + lch;
    const float* Wp = W + (size_t)(n0 + lrow) * HID + lch;

    float4 pa[4], pb[4];
#pragma unroll
    for (int i = 0; i < 4; i++) {
        pa[i] = *(const float4*)(Xp + (size_t)i * 32 * HID);
        pb[i] = *(const float4*)(Wp + (size_t)i * 32 * HID);
    }
    store_stage(dsm, pa, pb, lrow, lch);
    __syncthreads();

    int s = 0;
    for (int k0 = 0; k0 < HID; k0 += 32, s ^= 1) {
        const bool more = (k0 + 32 < HID);
        if (more) {
#pragma unroll
            for (int i = 0; i < 4; i++) {
                pa[i] = *(const float4*)(Xp + k0 + 32 + (size_t)i * 32 * HID);
                pb[i] = *(const float4*)(Wp + k0 + 32 + (size_t)i * 32 * HID);
            }
        }

        const uint32_t sb = base + (uint32_t)s * GSTG_BYTES;
#pragma unroll
        for (int ks = 0; ks < 32; ks += 16) {
            uint32_t ah[4][4], al[4][4];
#pragma unroll
            for (int mt = 0; mt < 4; mt++) {
                uint32_t off = aOff + (uint32_t)(mt * 16 * LDT + ks) * 2;
                ldsm4(ah[mt], sb + off);
                ldsm4(al[mt], sb + ALO_B + off);
            }
#pragma unroll
            for (int nt = 0; nt < 4; nt++) {
                uint32_t off = bOff + (uint32_t)(nt * 8 * LDT + ks) * 2;
                uint32_t bh[2], bl[2];
                ldsm2(bh, sb + BHI_B + off);
                ldsm2(bl, sb + BLO_B + off);
#pragma unroll
                for (int mt = 0; mt < 4; mt++) {
                    mma_bf16(acc[mt][nt], ah[mt], bh);
                    mma_bf16(acc[mt][nt], al[mt], bh);
                    mma_bf16(acc[mt][nt], ah[mt], bl);
                }
            }
        }

        if (more)
            store_stage(dsm + (s ^ 1) * GSTG_ELEMS, pa, pb, lrow, lch);
        __syncthreads();
    }

    const int g = lane >> 2;
    const int t = (lane & 3) * 2;
#pragma unroll
    for (int nt = 0; nt < 4; nt++) {
        const int nc = n0 + wn + nt * 8 + t;
        float2 bb = *(const float2*)(bias + nc);
#pragma unroll
        for (int mt = 0; mt < 4; mt++) {
            const int mr = m0 + wm + mt * 16 + g;
            float2 o0 = make_float2(acc[mt][nt][0] + bb.x, acc[mt][nt][1] + bb.y);
            float2 o1 = make_float2(acc[mt][nt][2] + bb.x, acc[mt][nt][3] + bb.y);
            *(float2*)(out + (size_t)mr * HID + nc)       = o0;
            *(float2*)(out + (size_t)(mr + 8) * HID + nc) = o1;
        }
    }
}

__global__ void __launch_bounds__(256) qkv_kernel(const float* __restrict__ X,
    const float* __restrict__ Wq, const float* __restrict__ bq,
    const float* __restrict__ Wk, const float* __restrict__ bk,
    const float* __restrict__ Wv, const float* __restrict__ bv)
{
    const float* W; const float* b; float* out;
    if (blockIdx.z == 0)      { W = Wq; b = bq; out = g_q; }
    else if (blockIdx.z == 1) { W = Wk; b = bk; out = g_k; }
    else                      { W = Wv; b = bv; out = g_v; }
    gemm_mma(X, W, b, out);
}

__global__ void __launch_bounds__(256) oproj_kernel(const float* __restrict__ Wo,
                                                    const float* __restrict__ bo,
                                                    float* __restrict__ out)
{
    gemm_mma(g_attn, Wo, bo, out);
}

// ---------------------------------------------------------------------------
// Tensor-core flash attention, v4: 2-stage K/V smem pipeline.
// CTA: 128 q-rows x one (b,h); 8 warps x 16 q-rows; 32-key tiles;
// launch_bounds(256,2) -> 2 CTAs/SM. Bias pre-fused. exp via MUFU.
// ---------------------------------------------------------------------------
#define ATILE (32*ALD)          // elems per K/V stage array

__global__ void __launch_bounds__(256, 2) attn_kernel()
{
    __shared__ __align__(16) __nv_bfloat16 sKh[2*ATILE];
    __shared__ __align__(16) __nv_bfloat16 sKl[2*ATILE];
    __shared__ __align__(16) __nv_bfloat16 sVh[2*ATILE];
    __shared__ __align__(16) __nv_bfloat16 sVl[2*ATILE];

    const float* __restrict__ bias = g_bias;

    const int tid  = threadIdx.x;
    const int lane = tid & 31;
    const int w    = tid >> 5;
    const int g    = lane >> 2;
    const int t    = lane & 3;
    const int b    = blockIdx.y / NH;
    const int h    = blockIdx.y % NH;
    const int q0   = blockIdx.x * 128;

    const uint32_t kHb = (uint32_t)__cvta_generic_to_shared(sKh);
    const uint32_t kLb = (uint32_t)__cvta_generic_to_shared(sKl);
    const uint32_t vHb = (uint32_t)__cvta_generic_to_shared(sVh);
    const uint32_t vLb = (uint32_t)__cvta_generic_to_shared(sVl);
    const uint32_t STGB = ATILE * 2;   // stage stride in bytes

    const int qrow0 = q0 + w*16 + g;

    // loader mapping for K/V tiles
    const int lr = tid >> 3;            // 0..31
    const int d0 = (tid & 7) * 8;
    const int e  = lr*ALD + d0;
    const float* kbase = g_k + ((size_t)(b*SQ + lr))*HID + h*64 + d0;
    const float* vbase = g_v + ((size_t)(b*SQ + lr))*HID + h*64 + d0;

    // ---- Q fragments direct from gmem (scaled by 1/8), split hi/lo ----
    uint32_t qh[4][4], ql[4][4];
    {
        const float* rowA = g_q + ((size_t)(b*SQ + qrow0))*HID + h*64;
        const float* rowB = rowA + (size_t)8*HID;
#pragma unroll
        for (int ks = 0; ks < 4; ks++) {
            const int c = ks*16 + t*2;
            float2 v;
            v = *(const float2*)(rowA + c);
            split2(v.x*0.125f, v.y*0.125f, qh[ks][0], ql[ks][0]);
            v = *(const float2*)(rowB + c);
            split2(v.x*0.125f, v.y*0.125f, qh[ks][1], ql[ks][1]);
            v = *(const float2*)(rowA + c + 8);
            split2(v.x*0.125f, v.y*0.125f, qh[ks][2], ql[ks][2]);
            v = *(const float2*)(rowB + c + 8);
            split2(v.x*0.125f, v.y*0.125f, qh[ks][3], ql[ks][3]);
        }
    }

    // ---- prologue: stage 0 = key tile 0 ----
    {
#pragma unroll
        for (int i = 0; i < 2; i++) {
            __nv_bfloat162 h0, h1, l0, l1;
            split4(*(const float4*)(kbase + i*4), h0, h1, l0, l1);
            *(__nv_bfloat162*)(sKh + e + i*4)     = h0;
            *(__nv_bfloat162*)(sKh + e + i*4 + 2) = h1;
            *(__nv_bfloat162*)(sKl + e + i*4)     = l0;
            *(__nv_bfloat162*)(sKl + e + i*4 + 2) = l1;
            split4(*(const float4*)(vbase + i*4), h0, h1, l0, l1);
            *(__nv_bfloat162*)(sVh + e + i*4)     = h0;
            *(__nv_bfloat162*)(sVh + e + i*4 + 2) = h1;
            *(__nv_bfloat162*)(sVl + e + i*4)     = l0;
            *(__nv_bfloat162*)(sVl + e + i*4 + 2) = l1;
        }
    }
    __syncthreads();

    float m_i[2] = {-1e30f, -1e30f};
    float l_i[2] = {0.f, 0.f};
    float oacc[8][4];
#pragma unroll
    for (int nt = 0; nt < 8; nt++)
#pragma unroll
        for (int r = 0; r < 4; r++) oacc[nt][r] = 0.f;

    const size_t bias0 = ((size_t)b*SQ + qrow0) * SQ;
    const size_t bias1 = bias0 + 8*SQ;

    for (int kt = 0; kt < 32; kt++) {
        const int k0 = kt * 32;
        const int cur = kt & 1;
        const bool more = (kt + 1 < 32);
        const uint32_t cb = (uint32_t)cur * STGB;

        // ---- fused bias into score fragments (C init) ----
        float sv[4][4];
#pragma unroll
        for (int nt = 0; nt < 4; nt++) {
            const size_t c = k0 + nt*8 + t*2;
            float2 v0 = *(const float2*)(bias + bias0 + c);
            float2 v1 = *(const float2*)(bias + bias1 + c);
            sv[nt][0] = v0.x; sv[nt][1] = v0.y;
            sv[nt][2] = v1.x; sv[nt][3] = v1.y;
        }

        // ---- prefetch next K/V tile into registers ----
        float4 nk[2], nv[2];
        if (more) {
            const float* kp = kbase + (size_t)(k0 + 32) * HID;
            const float* vp = vbase + (size_t)(k0 + 32) * HID;
#pragma unroll
            for (int i = 0; i < 2; i++) {
                nk[i] = *(const float4*)(kp + i*4);
                nv[i] = *(const float4*)(vp + i*4);
            }
        }

        // ---- scores += Q.K^T (split: hh + lh + hl) ----
#pragma unroll
        for (int ks = 0; ks < 4; ks++) {
#pragma unroll
            for (int nt = 0; nt < 4; nt++) {
                const uint32_t boff = cb + (uint32_t)((nt*8 + (lane & 7)) * ALD
                                     + ((lane >> 3) & 1) * 8 + ks*16) * 2;
                uint32_t kh[2], kl[2];
                ldsm2(kh, kHb + boff);
                ldsm2(kl, kLb + boff);
                mma_bf16(sv[nt], qh[ks], kh);
                mma_bf16(sv[nt], ql[ks], kh);
                mma_bf16(sv[nt], qh[ks], kl);
            }
        }

        // ---- store next tile into other stage ----
        if (more) {
            const int eo = (cur ^ 1) * ATILE + e;
#pragma unroll
            for (int i = 0; i < 2; i++) {
                __nv_bfloat162 h0, h1, l0, l1;
                split4(nk[i], h0, h1, l0, l1);
                *(__nv_bfloat162*)(sKh + eo + i*4)     = h0;
                *(__nv_bfloat162*)(sKh + eo + i*4 + 2) = h1;
                *(__nv_bfloat162*)(sKl + eo + i*4)     = l0;
                *(__nv_bfloat162*)(sKl + eo + i*4 + 2) = l1;
                split4(nv[i], h0, h1, l0, l1);
                *(__nv_bfloat162*)(sVh + eo + i*4)     = h0;
                *(__nv_bfloat162*)(sVh + eo + i*4 + 2) = h1;
                *(__nv_bfloat162*)(sVl + eo + i*4)     = l0;
                *(__nv_bfloat162*)(sVl + eo + i*4 + 2) = l1;
            }
        }

        // ---- online softmax (rows g and g+8; reduce over quad lanes) ----
        float mx0 = sv[0][0], mx1 = sv[0][2];
#pragma unroll
        for (int nt = 0; nt < 4; nt++) {
            mx0 = fmaxf(mx0, fmaxf(sv[nt][0], sv[nt][1]));
            mx1 = fmaxf(mx1, fmaxf(sv[nt][2], sv[nt][3]));
        }
        mx0 = fmaxf(mx0, __shfl_xor_sync(0xffffffffu, mx0, 1));
        mx0 = fmaxf(mx0, __shfl_xor_sync(0xffffffffu, mx0, 2));
        mx1 = fmaxf(mx1, __shfl_xor_sync(0xffffffffu, mx1, 1));
        mx1 = fmaxf(mx1, __shfl_xor_sync(0xffffffffu, mx1, 2));

        const float mn0 = fmaxf(m_i[0], mx0);
        const float mn1 = fmaxf(m_i[1], mx1);
        const float al0 = fexp2((m_i[0] - mn0) * LOG2E);
        const float al1 = fexp2((m_i[1] - mn1) * LOG2E);
        const float ml0 = mn0 * LOG2E;
        const float ml1 = mn1 * LOG2E;
        float ps0 = 0.f, ps1 = 0.f;
#pragma unroll
        for (int nt = 0; nt < 4; nt++) {
            sv[nt][0] = fexp2(fmaf(sv[nt][0], LOG2E, -ml0));
            sv[nt][1] = fexp2(fmaf(sv[nt][1], LOG2E, -ml0));
            sv[nt][2] = fexp2(fmaf(sv[nt][2], LOG2E, -ml1));
            sv[nt][3] = fexp2(fmaf(sv[nt][3], LOG2E, -ml1));
            ps0 += sv[nt][0] + sv[nt][1];
            ps1 += sv[nt][2] + sv[nt][3];
        }
        ps0 += __shfl_xor_sync(0xffffffffu, ps0, 1);
        ps0 += __shfl_xor_sync(0xffffffffu, ps0, 2);
        ps1 += __shfl_xor_sync(0xffffffffu, ps1, 1);
        ps1 += __shfl_xor_sync(0xffffffffu, ps1, 2);
        l_i[0] = l_i[0]*al0 + ps0;  m_i[0] = mn0;
        l_i[1] = l_i[1]*al1 + ps1;  m_i[1] = mn1;
#pragma unroll
        for (int nt = 0; nt < 8; nt++) {
            oacc[nt][0] *= al0; oacc[nt][1] *= al0;
            oacc[nt][2] *= al1; oacc[nt][3] *= al1;
        }

        // ---- PV: repack P per-ks, then MMA (V^T via ldmatrix.trans) ----
#pragma unroll
        for (int ks = 0; ks < 2; ks++) {
            uint32_t ph[4], pl[4];
            split2(sv[2*ks][0],   sv[2*ks][1],   ph[0], pl[0]);
            split2(sv[2*ks][2],   sv[2*ks][3],   ph[1], pl[1]);
            split2(sv[2*ks+1][0], sv[2*ks+1][1], ph[2], pl[2]);
            split2(sv[2*ks+1][2], sv[2*ks+1][3], ph[3], pl[3]);
#pragma unroll
            for (int nt = 0; nt < 8; nt++) {
                const uint32_t voff = cb + (uint32_t)((ks*16 + (lane & 15)) * ALD + nt*8) * 2;
                uint32_t vh[2], vl[2];
                ldsm2t(vh, vHb + voff);
                ldsm2t(vl, vLb + voff);
                mma_bf16(oacc[nt], ph, vh);
                mma_bf16(oacc[nt], pl, vh);
                mma_bf16(oacc[nt], ph, vl);
            }
        }

        __syncthreads();   // stage swap barrier
    }

    // ---- normalize + write ----
    const float inv0 = 1.f / l_i[0];
    const float inv1 = 1.f / l_i[1];
    float* o0 = g_attn + ((size_t)(b*SQ + qrow0))*HID + h*64 + t*2;
    float* o1 = o0 + (size_t)8 * HID;
#pragma unroll
    for (int nt = 0; nt < 8; nt++) {
        *(float2*)(o0 + nt*8) = make_float2(oacc[nt][0]*inv0, oacc[nt][1]*inv0);
        *(float2*)(o1 + nt*8) = make_float2(oacc[nt][2]*inv1, oacc[nt][3]*inv1);
    }
}

// ---------------------------------------------------------------------------
extern "C" void kernel_launch(void* const* d_in, const int* in_sizes, int n_in,
                              void* d_out, int out_size)
{
    const float* x  = (const float*)d_in[0];
    const float* sp = (const float*)d_in[1];
    const float* ed = (const float*)d_in[2];
    const unsigned char* mk = (const unsigned char*)d_in[3];
    const float* Wq = (const float*)d_in[4];
    const float* bq = (const float*)d_in[5];
    const float* Wk = (const float*)d_in[6];
    const float* bk = (const float*)d_in[7];
    const float* Wv = (const float*)d_in[8];
    const float* bv = (const float*)d_in[9];
    const float* Wo = (const float*)d_in[10];
    const float* bo = (const float*)d_in[11];
    float* out = (float*)d_out;

    cudaFuncSetAttribute(qkv_kernel,  cudaFuncAttributeMaxDynamicSharedMemorySize, GSMEM_BYTES);
    cudaFuncSetAttribute(oproj_kernel, cudaFuncAttributeMaxDynamicSharedMemorySize, GSMEM_BYTES);

    bias_kernel<<<(NB*SQ*SQ)/(256*4), 256>>>(sp, ed, mk);

    dim3 gq(MROWS/128, HID/128, 3);     // 64 x 6 x 3
    qkv_kernel<<<gq, 256, GSMEM_BYTES>>>(x, Wq, bq, Wk, bk, Wv, bv);

    dim3 ga(SQ/128, NB*NH);             // 8 x 96
    attn_kernel<<<ga, 256>>>();

    dim3 go(MROWS/128, HID/128);        // 64 x 6
    oproj_kernel<<<go, 256, GSMEM_BYTES>>>(Wo, bo, out);
}

// round 10
// speedup vs baseline: 1.0352x; 1.0352x over previous
#include <cuda_runtime.h>
#include <cuda_bf16.h>
#include <stdint.h>

#define NH   12
#define SQ   1024
#define NB   8
#define HID  768
#define MROWS (NB*SQ)   // 8192
#define ALD  72         // attention K/V tiles: 64 d-cols + 8 pad
#define BIAS4 ((size_t)NB*SQ*SQ/4)   // 2,097,152 float4
#define BIAS_PER_CTA 1821

// GEMM smem: stage = Ahi,Alo,Bhi,Blo 128x64 bf16 tiles (SW128, 128B rows)
#define GTILE_B   16384
#define GSTAGE_B  (4*GTILE_B)       // 64KB
#define GSMEM     (2*GSTAGE_B)      // 128KB dynamic

// Scratch (allocation-free rule: device globals)
__device__ float g_q[MROWS*HID];
__device__ __nv_bfloat16 g_khi[MROWS*HID], g_klo[MROWS*HID];
__device__ __nv_bfloat16 g_vhi[MROWS*HID], g_vlo[MROWS*HID];
__device__ __nv_bfloat16 g_ahi[MROWS*HID], g_alo[MROWS*HID];
__device__ __nv_bfloat16 g_xhi[MROWS*HID], g_xlo[MROWS*HID];
__device__ __nv_bfloat16 g_wqh[HID*HID], g_wql[HID*HID];
__device__ __nv_bfloat16 g_wkh[HID*HID], g_wkl[HID*HID];
__device__ __nv_bfloat16 g_wvh[HID*HID], g_wvl[HID*HID];
__device__ __nv_bfloat16 g_woh[HID*HID], g_wol[HID*HID];
__device__ float g_bias[(size_t)NB*SQ*SQ];

// ---------------------------------------------------------------------------
// Primitives
// ---------------------------------------------------------------------------
__device__ __forceinline__ void mma_bf16(float* d, const uint32_t* a, const uint32_t* b)
{
    asm volatile(
        "mma.sync.aligned.m16n8k16.row.col.f32.bf16.bf16.f32 "
        "{%0,%1,%2,%3},{%4,%5,%6,%7},{%8,%9},{%0,%1,%2,%3};"
        : "+f"(d[0]), "+f"(d[1]), "+f"(d[2]), "+f"(d[3])
        : "r"(a[0]), "r"(a[1]), "r"(a[2]), "r"(a[3]), "r"(b[0]), "r"(b[1]));
}
__device__ __forceinline__ void ldsm4(uint32_t* r, uint32_t addr)
{
    asm volatile("ldmatrix.sync.aligned.m8n8.x4.shared.b16 {%0,%1,%2,%3},[%4];"
                 : "=r"(r[0]), "=r"(r[1]), "=r"(r[2]), "=r"(r[3]) : "r"(addr));
}
__device__ __forceinline__ void ldsm2(uint32_t* r, uint32_t addr)
{
    asm volatile("ldmatrix.sync.aligned.m8n8.x2.shared.b16 {%0,%1},[%2];"
                 : "=r"(r[0]), "=r"(r[1]) : "r"(addr));
}
__device__ __forceinline__ void ldsm2t(uint32_t* r, uint32_t addr)
{
    asm volatile("ldmatrix.sync.aligned.m8n8.x2.trans.shared.b16 {%0,%1},[%2];"
                 : "=r"(r[0]), "=r"(r[1]) : "r"(addr));
}
__device__ __forceinline__ void cp16(uint32_t dst, const void* src)
{
    asm volatile("cp.async.cg.shared.global [%0], [%1], 16;"
                 :: "r"(dst), "l"(src) : "memory");
}
#define CP_COMMIT() asm volatile("cp.async.commit_group;" ::: "memory")
#define CP_WAIT(n)  asm volatile("cp.async.wait_group %0;" :: "n"(n) : "memory")
__device__ __forceinline__ float fexp2(float x)
{
    float y;
    asm("ex2.approx.ftz.f32 %0, %1;" : "=f"(y) : "f"(x));
    return y;
}
#define LOG2E 1.4426950408889634f
#define SMEM_SWZ(off) ((off) ^ (((off) >> 3) & 0x70))

// split x into hi (bf16) + lo (bf16 of residual)
__device__ __forceinline__ void split4(float4 v, __nv_bfloat162& h0, __nv_bfloat162& h1,
                                       __nv_bfloat162& l0, __nv_bfloat162& l1)
{
    __nv_bfloat16 hx = __float2bfloat16_rn(v.x);
    __nv_bfloat16 hy = __float2bfloat16_rn(v.y);
    __nv_bfloat16 hz = __float2bfloat16_rn(v.z);
    __nv_bfloat16 hw = __float2bfloat16_rn(v.w);
    h0 = __nv_bfloat162(hx, hy);
    h1 = __nv_bfloat162(hz, hw);
    l0 = __nv_bfloat162(__float2bfloat16_rn(v.x - __bfloat162float(hx)),
                        __float2bfloat16_rn(v.y - __bfloat162float(hy)));
    l1 = __nv_bfloat162(__float2bfloat16_rn(v.z - __bfloat162float(hz)),
                        __float2bfloat16_rn(v.w - __bfloat162float(hw)));
}
__device__ __forceinline__ void split2(float x, float y, uint32_t& hi, uint32_t& lo)
{
    __nv_bfloat16 hx = __float2bfloat16_rn(x);
    __nv_bfloat16 hy = __float2bfloat16_rn(y);
    __nv_bfloat162 h(hx, hy);
    __nv_bfloat162 l(__float2bfloat16_rn(x - __bfloat162float(hx)),
                     __float2bfloat16_rn(y - __bfloat162float(hy)));
    hi = *(uint32_t*)&h;
    lo = *(uint32_t*)&l;
}

// ---------------------------------------------------------------------------
// Pre-split fp32 -> bf16 hi/lo. which: 0=x, 1=Wq, 2=Wk, 3=Wv, 4=Wo
// ---------------------------------------------------------------------------
__global__ void __launch_bounds__(256) split_kernel(const float* __restrict__ src,
                                                    int which, int n4)
{
    const int i = blockIdx.x * 256 + threadIdx.x;
    if (i >= n4) return;
    __nv_bfloat16 *hi, *lo;
    switch (which) {
        case 0: hi = g_xhi; lo = g_xlo; break;
        case 1: hi = g_wqh; lo = g_wql; break;
        case 2: hi = g_wkh; lo = g_wkl; break;
        case 3: hi = g_wvh; lo = g_wvl; break;
        default: hi = g_woh; lo = g_wol; break;
    }
    float4 v = ((const float4*)src)[i];
    __nv_bfloat162 h0, h1, l0, l1;
    split4(v, h0, h1, l0, l1);
    uint2 uh, ul;
    uh.x = *(uint32_t*)&h0; uh.y = *(uint32_t*)&h1;
    ul.x = *(uint32_t*)&l0; ul.y = *(uint32_t*)&l1;
    *(uint2*)(hi + (size_t)i*4) = uh;
    *(uint2*)(lo + (size_t)i*4) = ul;
}

// ---------------------------------------------------------------------------
// bf16 tensor-core GEMM, cp.async 2-stage ring, pure ldsm/mma hot loop.
// out[m][n] = sum_k A[m][k]*B[n][k] + bias[n], A=Ah+Al, B=Bh+Bl.
// outf!=null -> fp32 out; else bf16 hi/lo out. Optionally fuses the bias
// precompute (g_bias = sp+ed, mask) spread across slab iterations.
// ---------------------------------------------------------------------------
__device__ __forceinline__ void gemm_cp(
    const __nv_bfloat16* __restrict__ Ah, const __nv_bfloat16* __restrict__ Al,
    const __nv_bfloat16* __restrict__ Bh, const __nv_bfloat16* __restrict__ Bl,
    const float* __restrict__ bias,
    float* __restrict__ outf,
    __nv_bfloat16* __restrict__ ohi, __nv_bfloat16* __restrict__ olo,
    const float4* __restrict__ bsp, const float4* __restrict__ bed,
    const uint32_t* __restrict__ bmk, int cid)
{
    extern __shared__ __align__(16) char dsm[];
    const uint32_t sb0 = (uint32_t)__cvta_generic_to_shared(dsm);
    const int tid  = threadIdx.x;
    const int lane = tid & 31;
    const int wid  = tid >> 5;
    const int wm   = (wid >> 2) * 64;
    const int wn   = (wid & 3) * 32;
    const int m0   = blockIdx.x * 128;
    const int n0   = blockIdx.y * 128;
    const int lr   = tid >> 3;        // 0..31 loader row
    const int lc   = tid & 7;         // 16B chunk within 128B row

    const size_t aoff0 = (size_t)(m0 + lr) * HID + lc * 8;
    const size_t boff0 = (size_t)(n0 + lr) * HID + lc * 8;

    float acc[4][4][4];
#pragma unroll
    for (int mt = 0; mt < 4; mt++)
#pragma unroll
        for (int nt = 0; nt < 4; nt++)
#pragma unroll
            for (int r = 0; r < 4; r++) acc[mt][nt][r] = 0.f;

    auto issue = [&](int p) {
        const uint32_t stg = (uint32_t)(p & 1) * GSTAGE_B;
#pragma unroll
        for (int j = 0; j < 4; j++) {
            const uint32_t sw = stg + SMEM_SWZ((uint32_t)((lr + 32*j)*128 + lc*16));
            const size_t ao = aoff0 + (size_t)32*j*HID + p*64;
            const size_t bo = boff0 + (size_t)32*j*HID + p*64;
            cp16(sb0 + sw,             Ah + ao);
            cp16(sb0 + GTILE_B + sw,   Al + ao);
            cp16(sb0 + 2*GTILE_B + sw, Bh + bo);
            cp16(sb0 + 3*GTILE_B + sw, Bl + bo);
        }
        CP_COMMIT();
    };

    issue(0);
    issue(1);

    for (int s = 0; s < 12; s++) {
        if (s < 11) { CP_WAIT(1); } else { CP_WAIT(0); }
        __syncthreads();

        const uint32_t sbA = sb0 + (uint32_t)(s & 1) * GSTAGE_B;
#pragma unroll
        for (int ks = 0; ks < 4; ks++) {
            uint32_t ah[4][4], al[4][4];
#pragma unroll
            for (int mt = 0; mt < 4; mt++) {
                const uint32_t off = SMEM_SWZ((uint32_t)((wm + mt*16 + (lane & 15))*128
                                              + ks*32 + (lane >> 4)*16));
                ldsm4(ah[mt], sbA + off);
                ldsm4(al[mt], sbA + GTILE_B + off);
            }
#pragma unroll
            for (int nt = 0; nt < 4; nt++) {
                const uint32_t offb = SMEM_SWZ((uint32_t)((wn + nt*8 + (lane & 7))*128
                                               + ks*32 + ((lane >> 3) & 1)*16));
                uint32_t bh[2], bl[2];
                ldsm2(bh, sbA + 2*GTILE_B + offb);
                ldsm2(bl, sbA + 3*GTILE_B + offb);
#pragma unroll
                for (int mt = 0; mt < 4; mt++) {
                    mma_bf16(acc[mt][nt], ah[mt], bh);
                    mma_bf16(acc[mt][nt], al[mt], bh);
                    mma_bf16(acc[mt][nt], ah[mt], bl);
                }
            }
        }
        __syncthreads();

        if (s + 2 < 12) issue(s + 2);

        // fused bias precompute chunk (qkv only)
        if (bsp != nullptr && s < 8) {
            const int j = s*256 + tid;
            if (j < BIAS_PER_CTA) {
                const size_t idx = (size_t)cid * BIAS_PER_CTA + j;
                if (idx < BIAS4) {
                    float4 sv_ = bsp[idx];
                    float4 ev  = bed[idx];
                    uint32_t m = bmk[idx];
                    float4 o;
                    o.x = (m & 0x000000ffu) ? -1e30f : sv_.x + ev.x;
                    o.y = (m & 0x0000ff00u) ? -1e30f : sv_.y + ev.y;
                    o.z = (m & 0x00ff0000u) ? -1e30f : sv_.z + ev.z;
                    o.w = (m & 0xff000000u) ? -1e30f : sv_.w + ev.w;
                    ((float4*)g_bias)[idx] = o;
                }
            }
        }
    }

    // epilogue
    const int g = lane >> 2;
    const int t = (lane & 3) * 2;
#pragma unroll
    for (int nt = 0; nt < 4; nt++) {
        const int nc = n0 + wn + nt*8 + t;
        float2 bb = *(const float2*)(bias + nc);
#pragma unroll
        for (int mt = 0; mt < 4; mt++) {
            const int mr = m0 + wm + mt*16 + g;
            float v0 = acc[mt][nt][0] + bb.x, v1 = acc[mt][nt][1] + bb.y;
            float v2 = acc[mt][nt][2] + bb.x, v3 = acc[mt][nt][3] + bb.y;
            if (outf != nullptr) {
                *(float2*)(outf + (size_t)mr*HID + nc)     = make_float2(v0, v1);
                *(float2*)(outf + (size_t)(mr+8)*HID + nc) = make_float2(v2, v3);
            } else {
                uint32_t hi, lo;
                split2(v0, v1, hi, lo);
                *(uint32_t*)(ohi + (size_t)mr*HID + nc) = hi;
                *(uint32_t*)(olo + (size_t)mr*HID + nc) = lo;
                split2(v2, v3, hi, lo);
                *(uint32_t*)(ohi + (size_t)(mr+8)*HID + nc) = hi;
                *(uint32_t*)(olo + (size_t)(mr+8)*HID + nc) = lo;
            }
        }
    }
}

__global__ void __launch_bounds__(256) qkv_kernel(
    const float* __restrict__ bq, const float* __restrict__ bk,
    const float* __restrict__ bv,
    const float4* __restrict__ bsp, const float4* __restrict__ bed,
    const uint32_t* __restrict__ bmk)
{
    const int cid = blockIdx.x + 64*blockIdx.y + 384*blockIdx.z;
    if (blockIdx.z == 0)
        gemm_cp(g_xhi, g_xlo, g_wqh, g_wql, bq, g_q, nullptr, nullptr,
                bsp, bed, bmk, cid);
    else if (blockIdx.z == 1)
        gemm_cp(g_xhi, g_xlo, g_wkh, g_wkl, bk, nullptr, g_khi, g_klo,
                bsp, bed, bmk, cid);
    else
        gemm_cp(g_xhi, g_xlo, g_wvh, g_wvl, bv, nullptr, g_vhi, g_vlo,
                bsp, bed, bmk, cid);
}

__global__ void __launch_bounds__(256) oproj_kernel(const float* __restrict__ bo,
                                                    float* __restrict__ out)
{
    gemm_cp(g_ahi, g_alo, g_woh, g_wol, bo, out, nullptr, nullptr,
            nullptr, nullptr, nullptr, 0);
}

// ---------------------------------------------------------------------------
// Tensor-core flash attention v5: cp.async 2-stage K/V ring (pre-split bf16
// inputs, zero conversion in the loop). CTA: 128 q x one (b,h); 8 warps x 16
// q-rows; 32-key tiles; 2 CTAs/SM. Bias pre-fused. exp via MUFU. Output
// written as bf16 hi/lo for oproj.
// ---------------------------------------------------------------------------
#define ATILE_B 4608   // 32*ALD*2 bytes per stage per array

__global__ void __launch_bounds__(256, 2) attn_kernel()
{
    __shared__ __align__(16) __nv_bfloat16 sKh[2*32*ALD];
    __shared__ __align__(16) __nv_bfloat16 sKl[2*32*ALD];
    __shared__ __align__(16) __nv_bfloat16 sVh[2*32*ALD];
    __shared__ __align__(16) __nv_bfloat16 sVl[2*32*ALD];

    const float* __restrict__ bias = g_bias;

    const int tid  = threadIdx.x;
    const int lane = tid & 31;
    const int w    = tid >> 5;
    const int g    = lane >> 2;
    const int t    = lane & 3;
    const int b    = blockIdx.y / NH;
    const int h    = blockIdx.y % NH;
    const int q0   = blockIdx.x * 128;

    const uint32_t kHb = (uint32_t)__cvta_generic_to_shared(sKh);
    const uint32_t kLb = (uint32_t)__cvta_generic_to_shared(sKl);
    const uint32_t vHb = (uint32_t)__cvta_generic_to_shared(sVh);
    const uint32_t vLb = (uint32_t)__cvta_generic_to_shared(sVl);

    // loader mapping: row 0..31, 16B chunk 0..7
    const int lrow = tid >> 3;
    const int lch  = tid & 7;
    const uint32_t ldst = (uint32_t)(lrow*ALD + lch*8) * 2;   // within-stage bytes
    const size_t lsrc0 = ((size_t)(b*SQ + lrow))*HID + h*64 + lch*8;

    auto issue = [&](int kt2) {
        const uint32_t d = (uint32_t)(kt2 & 1) * ATILE_B + ldst;
        const size_t src = lsrc0 + (size_t)kt2*32*HID;
        cp16(kHb + d, g_khi + src);
        cp16(kLb + d, g_klo + src);
        cp16(vHb + d, g_vhi + src);
        cp16(vLb + d, g_vlo + src);
        CP_COMMIT();
    };

    issue(0);
    issue(1);

    const int qrow0 = q0 + w*16 + g;

    // ---- Q fragments direct from gmem (scaled by 1/8), split hi/lo ----
    uint32_t qh[4][4], ql[4][4];
    {
        const float* rowA = g_q + ((size_t)(b*SQ + qrow0))*HID + h*64;
        const float* rowB = rowA + (size_t)8*HID;
#pragma unroll
        for (int ks = 0; ks < 4; ks++) {
            const int c = ks*16 + t*2;
            float2 v;
            v = *(const float2*)(rowA + c);
            split2(v.x*0.125f, v.y*0.125f, qh[ks][0], ql[ks][0]);
            v = *(const float2*)(rowB + c);
            split2(v.x*0.125f, v.y*0.125f, qh[ks][1], ql[ks][1]);
            v = *(const float2*)(rowA + c + 8);
            split2(v.x*0.125f, v.y*0.125f, qh[ks][2], ql[ks][2]);
            v = *(const float2*)(rowB + c + 8);
            split2(v.x*0.125f, v.y*0.125f, qh[ks][3], ql[ks][3]);
        }
    }

    float m_i[2] = {-1e30f, -1e30f};
    float l_i[2] = {0.f, 0.f};
    float oacc[8][4];
#pragma unroll
    for (int nt = 0; nt < 8; nt++)
#pragma unroll
        for (int r = 0; r < 4; r++) oacc[nt][r] = 0.f;

    const size_t bias0 = ((size_t)b*SQ + qrow0) * SQ;
    const size_t bias1 = bias0 + 8*SQ;

    for (int kt = 0; kt < 32; kt++) {
        const int k0 = kt * 32;
        const uint32_t cb = (uint32_t)(kt & 1) * ATILE_B;

        // ---- fused bias into score fragments (C init) ----
        float sv[4][4];
#pragma unroll
        for (int nt = 0; nt < 4; nt++) {
            const size_t c = k0 + nt*8 + t*2;
            float2 v0 = *(const float2*)(bias + bias0 + c);
            float2 v1 = *(const float2*)(bias + bias1 + c);
            sv[nt][0] = v0.x; sv[nt][1] = v0.y;
            sv[nt][2] = v1.x; sv[nt][3] = v1.y;
        }

        if (kt < 31) { CP_WAIT(1); } else { CP_WAIT(0); }
        __syncthreads();

        // ---- scores += Q.K^T (split: hh + lh + hl) ----
#pragma unroll
        for (int ks = 0; ks < 4; ks++) {
#pragma unroll
            for (int nt = 0; nt < 4; nt++) {
                const uint32_t boff = cb + (uint32_t)((nt*8 + (lane & 7)) * ALD
                                     + ((lane >> 3) & 1) * 8 + ks*16) * 2;
                uint32_t kh[2], kl[2];
                ldsm2(kh, kHb + boff);
                ldsm2(kl, kLb + boff);
                mma_bf16(sv[nt], qh[ks], kh);
                mma_bf16(sv[nt], ql[ks], kh);
                mma_bf16(sv[nt], qh[ks], kl);
            }
        }

        // ---- online softmax (rows g and g+8; reduce over quad lanes) ----
        float mx0 = sv[0][0], mx1 = sv[0][2];
#pragma unroll
        for (int nt = 0; nt < 4; nt++) {
            mx0 = fmaxf(mx0, fmaxf(sv[nt][0], sv[nt][1]));
            mx1 = fmaxf(mx1, fmaxf(sv[nt][2], sv[nt][3]));
        }
        mx0 = fmaxf(mx0, __shfl_xor_sync(0xffffffffu, mx0, 1));
        mx0 = fmaxf(mx0, __shfl_xor_sync(0xffffffffu, mx0, 2));
        mx1 = fmaxf(mx1, __shfl_xor_sync(0xffffffffu, mx1, 1));
        mx1 = fmaxf(mx1, __shfl_xor_sync(0xffffffffu, mx1, 2));

        const float mn0 = fmaxf(m_i[0], mx0);
        const float mn1 = fmaxf(m_i[1], mx1);
        const float al0 = fexp2((m_i[0] - mn0) * LOG2E);
        const float al1 = fexp2((m_i[1] - mn1) * LOG2E);
        const float ml0 = mn0 * LOG2E;
        const float ml1 = mn1 * LOG2E;
        float ps0 = 0.f, ps1 = 0.f;
#pragma unroll
        for (int nt = 0; nt < 4; nt++) {
            sv[nt][0] = fexp2(fmaf(sv[nt][0], LOG2E, -ml0));
            sv[nt][1] = fexp2(fmaf(sv[nt][1], LOG2E, -ml0));
            sv[nt][2] = fexp2(fmaf(sv[nt][2], LOG2E, -ml1));
            sv[nt][3] = fexp2(fmaf(sv[nt][3], LOG2E, -ml1));
            ps0 += sv[nt][0] + sv[nt][1];
            ps1 += sv[nt][2] + sv[nt][3];
        }
        ps0 += __shfl_xor_sync(0xffffffffu, ps0, 1);
        ps0 += __shfl_xor_sync(0xffffffffu, ps0, 2);
        ps1 += __shfl_xor_sync(0xffffffffu, ps1, 1);
        ps1 += __shfl_xor_sync(0xffffffffu, ps1, 2);
        l_i[0] = l_i[0]*al0 + ps0;  m_i[0] = mn0;
        l_i[1] = l_i[1]*al1 + ps1;  m_i[1] = mn1;
#pragma unroll
        for (int nt = 0; nt < 8; nt++) {
            oacc[nt][0] *= al0; oacc[nt][1] *= al0;
            oacc[nt][2] *= al1; oacc[nt][3] *= al1;
        }

        // ---- PV: repack P per-ks, then MMA (V^T via ldmatrix.trans) ----
#pragma unroll
        for (int ks = 0; ks < 2; ks++) {
            uint32_t ph[4], pl[4];
            split2(sv[2*ks][0],   sv[2*ks][1],   ph[0], pl[0]);
            split2(sv[2*ks][2],   sv[2*ks][3],   ph[1], pl[1]);
            split2(sv[2*ks+1][0], sv[2*ks+1][1], ph[2], pl[2]);
            split2(sv[2*ks+1][2], sv[2*ks+1][3], ph[3], pl[3]);
#pragma unroll
            for (int nt = 0; nt < 8; nt++) {
                const uint32_t voff = cb + (uint32_t)((ks*16 + (lane & 15)) * ALD + nt*8) * 2;
                uint32_t vh[2], vl[2];
                ldsm2t(vh, vHb + voff);
                ldsm2t(vl, vLb + voff);
                mma_bf16(oacc[nt], ph, vh);
                mma_bf16(oacc[nt], pl, vh);
                mma_bf16(oacc[nt], ph, vl);
            }
        }

        __syncthreads();                 // done reading this stage
        if (kt + 2 < 32) issue(kt + 2);  // refill it
    }

    // ---- normalize + write as bf16 hi/lo for oproj ----
    const float inv0 = 1.f / l_i[0];
    const float inv1 = 1.f / l_i[1];
    const size_t o0 = ((size_t)(b*SQ + qrow0))*HID + h*64 + t*2;
    const size_t o1 = o0 + (size_t)8*HID;
#pragma unroll
    for (int nt = 0; nt < 8; nt++) {
        uint32_t hi, lo;
        split2(oacc[nt][0]*inv0, oacc[nt][1]*inv0, hi, lo);
        *(uint32_t*)(g_ahi + o0 + nt*8) = hi;
        *(uint32_t*)(g_alo + o0 + nt*8) = lo;
        split2(oacc[nt][2]*inv1, oacc[nt][3]*inv1, hi, lo);
        *(uint32_t*)(g_ahi + o1 + nt*8) = hi;
        *(uint32_t*)(g_alo + o1 + nt*8) = lo;
    }
}

// ---------------------------------------------------------------------------
extern "C" void kernel_launch(void* const* d_in, const int* in_sizes, int n_in,
                              void* d_out, int out_size)
{
    const float* x  = (const float*)d_in[0];
    const float* sp = (const float*)d_in[1];
    const float* ed = (const float*)d_in[2];
    const unsigned char* mk = (const unsigned char*)d_in[3];
    const float* Wq = (const float*)d_in[4];
    const float* bq = (const float*)d_in[5];
    const float* Wk = (const float*)d_in[6];
    const float* bk = (const float*)d_in[7];
    const float* Wv = (const float*)d_in[8];
    const float* bv = (const float*)d_in[9];
    const float* Wo = (const float*)d_in[10];
    const float* bo = (const float*)d_in[11];
    float* out = (float*)d_out;

    cudaFuncSetAttribute(qkv_kernel,   cudaFuncAttributeMaxDynamicSharedMemorySize, GSMEM);
    cudaFuncSetAttribute(oproj_kernel, cudaFuncAttributeMaxDynamicSharedMemorySize, GSMEM);

    const int xn4 = MROWS*HID/4;     // 1,572,864
    const int wn4 = HID*HID/4;       // 147,456
    split_kernel<<<(xn4+255)/256, 256>>>(x,  0, xn4);
    split_kernel<<<(wn4+255)/256, 256>>>(Wq, 1, wn4);
    split_kernel<<<(wn4+255)/256, 256>>>(Wk, 2, wn4);
    split_kernel<<<(wn4+255)/256, 256>>>(Wv, 3, wn4);
    split_kernel<<<(wn4+255)/256, 256>>>(Wo, 4, wn4);

    dim3 gq(MROWS/128, HID/128, 3);     // 64 x 6 x 3
    qkv_kernel<<<gq, 256, GSMEM>>>(bq, bk, bv,
                                   (const float4*)sp, (const float4*)ed,
                                   (const uint32_t*)mk);

    dim3 ga(SQ/128, NB*NH);             // 8 x 96
    attn_kernel<<<ga, 256>>>();

    dim3 go(MROWS/128, HID/128);        // 64 x 6
    oproj_kernel<<<go, 256, GSMEM>>>(bo, out);
}